// round 2
// baseline (speedup 1.0000x reference)
#include <cuda_runtime.h>

#define BM 128
#define BN 64
#define DH 128
#define NT 256

typedef unsigned long long u64;

__device__ __forceinline__ u64 pk2(float x, float y) {
    u64 r; asm("mov.b64 %0, {%1, %2};" : "=l"(r) : "f"(x), "f"(y)); return r;
}
__device__ __forceinline__ void upk2(u64 v, float &x, float &y) {
    asm("mov.b64 {%0, %1}, %2;" : "=f"(x), "=f"(y) : "l"(v));
}
__device__ __forceinline__ void fma2(u64 &d, u64 a, u64 b) {
    asm("fma.rn.f32x2 %0, %1, %2, %0;" : "+l"(d) : "l"(a), "l"(b));
}
__device__ __forceinline__ u64 mul2(u64 a, u64 b) {
    u64 d; asm("mul.rn.f32x2 %0, %1, %2;" : "=l"(d) : "l"(a), "l"(b)); return d;
}
__device__ __forceinline__ float ex2f(float x) {
    float y; asm("ex2.approx.f32 %0, %1;" : "=f"(y) : "f"(x)); return y;
}

// shared memory layout (in floats)
#define QT_STRIDE 132
#define KT_STRIDE 68
#define ST_STRIDE 132
#define QT_OFF 0
#define KT_OFF (128 * 132)             // 16896
#define SV_OFF (KT_OFF + 128 * 68)     // 25600
#define ST_OFF (SV_OFF + 64 * 128)     // 33792
#define RED_OFF (ST_OFF + 64 * 132)    // 42240
#define M_OFF (RED_OFF + 8 * 128)      // 43264
#define A_OFF (M_OFF + 128)            // 43392
#define L_OFF (A_OFF + 128)            // 43520
#define SMEM_FLOATS (L_OFF + 128)      // 43648
#define SMEM_BYTES (SMEM_FLOATS * 4)   // 174592

__global__ void __launch_bounds__(NT, 1)
attn_fp32x2_kernel(const float* __restrict__ Q, const float* __restrict__ K,
                   const float* __restrict__ V, const int* __restrict__ vlen,
                   float* __restrict__ Out, int Nq, int Nk)
{
    extern __shared__ float sm[];
    float* QT  = sm + QT_OFF;    // [128 dims][132]: Q^T, row = dim, col = q-row
    float* KT  = sm + KT_OFF;    // [128 dims][68]:  K^T, row = dim, col = key
    float* SV  = sm + SV_OFF;    // [64 keys][128]:  V natural
    float* ST  = sm + ST_OFF;    // [64 keys][132]:  P^T, row = key, col = q-row
    float* RED = sm + RED_OFF;   // [8 warps][128 rows] partial max / sum
    float* MR  = sm + M_OFF;     // running row max (base-2 domain)
    float* AL  = sm + A_OFF;     // per-row rescale alpha
    float* LR  = sm + L_OFF;     // final row denominators

    const int tid  = threadIdx.x;
    const int lane = tid & 31;
    const int w    = tid >> 5;                 // warp 0..7
    const int b    = blockIdx.y;
    const int qb   = blockIdx.x;

    const int valid  = vlen[b];
    const int ntiles = (valid + BN - 1) / BN;  // block skipping: masked tail is exactly 0
    const float scale = 0.08838834764831845f * 1.4426950408889634f; // 1/sqrt(128) * log2(e)

    const float* Qb = Q + ((size_t)b * Nq + (size_t)qb * BM) * DH;
    const float* Kb = K + (size_t)b * Nk * DH;
    const float* Vb = V + (size_t)b * Nk * DH;

    // ---- load Q tile transposed into smem (conflict-free transposed stores) ----
    for (int i = tid; i < BM * (DH / 4); i += NT) {
        int q  = i & (BM - 1);
        int dg = i >> 7;
        float4 t = *(const float4*)(Qb + (size_t)q * DH + 4 * dg);
        QT[(4 * dg + 0) * QT_STRIDE + q] = t.x;
        QT[(4 * dg + 1) * QT_STRIDE + q] = t.y;
        QT[(4 * dg + 2) * QT_STRIDE + q] = t.z;
        QT[(4 * dg + 3) * QT_STRIDE + q] = t.w;
    }
    if (tid < BM) MR[tid] = -1e30f;

    // O accumulator: rows 4*lane+r, cols 16*w + 2*cp + {0,1}, packed f32x2 over cols
    u64 o2[4][8];
    #pragma unroll
    for (int r = 0; r < 4; r++)
        #pragma unroll
        for (int c = 0; c < 8; c++) o2[r][c] = 0ull;
    float l_reg = 0.0f;   // valid for tid < 128 (row = tid)

    for (int j = 0; j < ntiles; ++j) {
        __syncthreads();  // previous iteration's PV reads of ST/SV/KT complete
        const int kbase = j * BN;

        // ---- load K tile transposed ----
        for (int i = tid; i < BN * (DH / 4); i += NT) {
            int kk = i & (BN - 1);
            int dg = i >> 6;
            float4 t = *(const float4*)(Kb + (size_t)(kbase + kk) * DH + 4 * dg);
            KT[(4 * dg + 0) * KT_STRIDE + kk] = t.x;
            KT[(4 * dg + 1) * KT_STRIDE + kk] = t.y;
            KT[(4 * dg + 2) * KT_STRIDE + kk] = t.z;
            KT[(4 * dg + 3) * KT_STRIDE + kk] = t.w;
        }
        // ---- load V tile natural (coalesced float4) ----
        for (int i = tid; i < BN * (DH / 4); i += NT) {
            int kk = i >> 5;
            int dg = i & 31;
            *(float4*)(SV + kk * DH + 4 * dg) =
                *(const float4*)(Vb + (size_t)(kbase + kk) * DH + 4 * dg);
        }
        __syncthreads();

        // ---- S = Q K^T : thread tile rows 4*lane+r, cols 8*w + 2*cp + {0,1} ----
        u64 s2[4][4];
        #pragma unroll
        for (int r = 0; r < 4; r++)
            #pragma unroll
            for (int c = 0; c < 4; c++) s2[r][c] = 0ull;

        const float* qp = QT + 4 * lane;
        const float* kp = KT + 8 * w;
        #pragma unroll 4
        for (int kk = 0; kk < DH; kk++) {
            float4 a = *(const float4*)(qp + kk * QT_STRIDE);      // 4 q-rows, LDS.128
            u64 b0 = *(const u64*)(kp + kk * KT_STRIDE + 0);       // key pairs, LDS.64 broadcast
            u64 b1 = *(const u64*)(kp + kk * KT_STRIDE + 2);
            u64 b2 = *(const u64*)(kp + kk * KT_STRIDE + 4);
            u64 b3 = *(const u64*)(kp + kk * KT_STRIDE + 6);
            u64 a0 = pk2(a.x, a.x), a1 = pk2(a.y, a.y);
            u64 a2 = pk2(a.z, a.z), a3 = pk2(a.w, a.w);
            fma2(s2[0][0], a0, b0); fma2(s2[0][1], a0, b1); fma2(s2[0][2], a0, b2); fma2(s2[0][3], a0, b3);
            fma2(s2[1][0], a1, b0); fma2(s2[1][1], a1, b1); fma2(s2[1][2], a1, b2); fma2(s2[1][3], a1, b3);
            fma2(s2[2][0], a2, b0); fma2(s2[2][1], a2, b1); fma2(s2[2][2], a2, b2); fma2(s2[2][3], a2, b3);
            fma2(s2[3][0], a3, b0); fma2(s2[3][1], a3, b1); fma2(s2[3][2], a3, b2); fma2(s2[3][3], a3, b3);
        }

        // ---- unpack, scale + mask ----
        float s[4][8];
        #pragma unroll
        for (int r = 0; r < 4; r++)
            #pragma unroll
            for (int cp = 0; cp < 4; cp++)
                upk2(s2[r][cp], s[r][2 * cp], s[r][2 * cp + 1]);
        #pragma unroll
        for (int c = 0; c < 8; c++) {
            bool ok = (kbase + 8 * w + c) < valid;
            #pragma unroll
            for (int r = 0; r < 4; r++)
                s[r][c] = ok ? s[r][c] * scale : -1e30f;
        }

        // ---- per-warp partial row max ----
        #pragma unroll
        for (int r = 0; r < 4; r++) {
            float pm = s[r][0];
            #pragma unroll
            for (int c = 1; c < 8; c++) pm = fmaxf(pm, s[r][c]);
            RED[w * 128 + 4 * lane + r] = pm;
        }
        __syncthreads();

        // ---- pass1: reduce max across warps, compute alpha ----
        if (tid < BM) {
            float mt = RED[tid];
            #pragma unroll
            for (int ww = 1; ww < 8; ww++) mt = fmaxf(mt, RED[ww * 128 + tid]);
            float mo = MR[tid];
            float mn = fmaxf(mo, mt);
            MR[tid] = mn;
            AL[tid] = ex2f(mo - mn);
        }
        __syncthreads();

        // ---- P = exp2(s - m), partial row sums, write P^T, rescale O ----
        float mrow[4], al[4];
        #pragma unroll
        for (int r = 0; r < 4; r++) {
            mrow[r] = MR[4 * lane + r];
            al[r]   = AL[4 * lane + r];
        }
        float ps[4] = {0.f, 0.f, 0.f, 0.f};
        #pragma unroll
        for (int r = 0; r < 4; r++)
            #pragma unroll
            for (int c = 0; c < 8; c++) {
                float p = ex2f(s[r][c] - mrow[r]);
                s[r][c] = p;
                ps[r] += p;
            }
        #pragma unroll
        for (int c = 0; c < 8; c++)   // float4 over the 4 contiguous rows: conflict-free
            *(float4*)(ST + (8 * w + c) * ST_STRIDE + 4 * lane) =
                make_float4(s[0][c], s[1][c], s[2][c], s[3][c]);
        u64 alp[4];
        #pragma unroll
        for (int r = 0; r < 4; r++) alp[r] = pk2(al[r], al[r]);
        #pragma unroll
        for (int r = 0; r < 4; r++)
            #pragma unroll
            for (int c = 0; c < 8; c++) o2[r][c] = mul2(o2[r][c], alp[r]);
        #pragma unroll
        for (int r = 0; r < 4; r++)
            RED[w * 128 + 4 * lane + r] = ps[r];
        __syncthreads();

        // ---- pass2: row denominator update (runs alongside PV) ----
        if (tid < BM) {
            float st = 0.f;
            #pragma unroll
            for (int ww = 0; ww < 8; ww++) st += RED[ww * 128 + tid];
            l_reg = l_reg * AL[tid] + st;
        }

        // ---- O += P V : rows 4*lane+r, cols 16*w + 2*cp + {0,1} ----
        const float* pp = ST + 4 * lane;
        const float* vp = SV + 16 * w;
        #pragma unroll 2
        for (int kk = 0; kk < BN; kk++) {
            float4 p = *(const float4*)(pp + kk * ST_STRIDE);   // 4 rows, LDS.128
            u64 v0 = *(const u64*)(vp + kk * DH +  0);          // dim pairs, LDS.64 broadcast
            u64 v1 = *(const u64*)(vp + kk * DH +  2);
            u64 v2 = *(const u64*)(vp + kk * DH +  4);
            u64 v3 = *(const u64*)(vp + kk * DH +  6);
            u64 v4 = *(const u64*)(vp + kk * DH +  8);
            u64 v5 = *(const u64*)(vp + kk * DH + 10);
            u64 v6 = *(const u64*)(vp + kk * DH + 12);
            u64 v7 = *(const u64*)(vp + kk * DH + 14);
            u64 p0 = pk2(p.x, p.x), p1 = pk2(p.y, p.y);
            u64 p2 = pk2(p.z, p.z), p3 = pk2(p.w, p.w);
            fma2(o2[0][0], p0, v0); fma2(o2[0][1], p0, v1); fma2(o2[0][2], p0, v2); fma2(o2[0][3], p0, v3);
            fma2(o2[0][4], p0, v4); fma2(o2[0][5], p0, v5); fma2(o2[0][6], p0, v6); fma2(o2[0][7], p0, v7);
            fma2(o2[1][0], p1, v0); fma2(o2[1][1], p1, v1); fma2(o2[1][2], p1, v2); fma2(o2[1][3], p1, v3);
            fma2(o2[1][4], p1, v4); fma2(o2[1][5], p1, v5); fma2(o2[1][6], p1, v6); fma2(o2[1][7], p1, v7);
            fma2(o2[2][0], p2, v0); fma2(o2[2][1], p2, v1); fma2(o2[2][2], p2, v2); fma2(o2[2][3], p2, v3);
            fma2(o2[2][4], p2, v4); fma2(o2[2][5], p2, v5); fma2(o2[2][6], p2, v6); fma2(o2[2][7], p2, v7);
            fma2(o2[3][0], p3, v0); fma2(o2[3][1], p3, v1); fma2(o2[3][2], p3, v2); fma2(o2[3][3], p3, v3);
            fma2(o2[3][4], p3, v4); fma2(o2[3][5], p3, v5); fma2(o2[3][6], p3, v6); fma2(o2[3][7], p3, v7);
        }
    }

    // ---- finalize: divide by row denominator, store ----
    if (tid < BM) LR[tid] = l_reg;
    __syncthreads();
    #pragma unroll
    for (int r = 0; r < 4; r++) {
        float inv = 1.0f / LR[4 * lane + r];
        size_t rowoff = ((size_t)b * Nq + (size_t)qb * BM + 4 * lane + r) * DH + 16 * w;
        #pragma unroll
        for (int cp = 0; cp < 8; cp += 2) {
            float x0, x1, x2, x3;
            upk2(o2[r][cp],     x0, x1);
            upk2(o2[r][cp + 1], x2, x3);
            *(float4*)(Out + rowoff + 2 * cp) =
                make_float4(x0 * inv, x1 * inv, x2 * inv, x3 * inv);
        }
    }
}

extern "C" void kernel_launch(void* const* d_in, const int* in_sizes, int n_in,
                              void* d_out, int out_size) {
    const float* Q  = (const float*)d_in[0];
    const float* K  = (const float*)d_in[1];
    const float* V  = (const float*)d_in[2];
    const int* vlen = (const int*)d_in[3];
    float* Out = (float*)d_out;

    int B  = in_sizes[3];
    int Nq = in_sizes[0] / (B * DH);
    int Nk = in_sizes[1] / (B * DH);

    cudaFuncSetAttribute(attn_fp32x2_kernel,
                         cudaFuncAttributeMaxDynamicSharedMemorySize, SMEM_BYTES);

    dim3 grid((Nq + BM - 1) / BM, B);
    attn_fp32x2_kernel<<<grid, NT, SMEM_BYTES>>>(Q, K, V, vlen, Out, Nq, Nk);
}